// round 16
// baseline (speedup 1.0000x reference)
#include <cuda_runtime.h>
#include <cstdint>

#define NPIX 65536   // 256*256
#define HW   256
#define NSLICE 64

// ---------------- scratch (device globals; no allocation allowed) ----------
__device__ float g_kv_pre[2 * 96 * NPIX];   // dwconv-input channels only
__device__ float g_kv    [2 * 128 * NPIX];
__device__ float g_qh_pre[2 * 24 * NPIX];
__device__ float g_qh    [2 * 32 * NPIX];
__device__ float g_ql_pre[2 * 12 * NPIX];
__device__ float g_ql    [2 * 16 * NPIX];
__device__ float g_Gpart [8 * 3 * NSLICE * 64]; // [bh][grp][slice][c*16+d]
__device__ float g_SSpart[8 * NSLICE * 28];     // [bh][slice][k16|qh8|ql4]
__device__ unsigned g_McHi[2 * 192 * 36];  // folded proj hi bf16 pairs [b][o][kpair]
__device__ unsigned g_McLo[2 * 192 * 36];
__device__ unsigned g_WhiP[128 * 128];     // w_kv hi bf16, packed 2/k-pair
__device__ unsigned g_WloP[128 * 128];     // w_kv lo bf16
__device__ float g_WtQH  [128 * 32];
__device__ float g_WtQL  [64 * 16];
__device__ float g_dummy [32];

// ---------------- packed f32x2 helpers --------------------------------------
__device__ __forceinline__ unsigned long long pack2(float a) {
    unsigned long long r;
    asm("mov.b64 %0, {%1, %1};" : "=l"(r) : "f"(a));
    return r;
}
__device__ __forceinline__ void fma2(unsigned long long& d,
                                     unsigned long long a,
                                     unsigned long long b) {
    asm("fma.rn.f32x2 %0, %1, %2, %0;" : "+l"(d) : "l"(a), "l"(b));
}
__device__ __forceinline__ float2 unpack2(unsigned long long v) {
    float2 f;
    asm("mov.b64 {%0, %1}, %2;" : "=f"(f.x), "=f"(f.y) : "l"(v));
    return f;
}

// ---------------- cp.async helpers ------------------------------------------
__device__ __forceinline__ void cp16(uint32_t s, const void* g) {
    asm volatile("cp.async.cg.shared.global [%0], [%1], 16;" :: "r"(s), "l"(g));
}
__device__ __forceinline__ void cp_commit() {
    asm volatile("cp.async.commit_group;" ::: "memory");
}
template<int N>
__device__ __forceinline__ void cp_wait() {
    asm volatile("cp.async.wait_group %0;" :: "n"(N) : "memory");
}

// ---------------- mma.sync bf16 helpers --------------------------------------
__device__ __forceinline__ void mma_bf16(float* d, const uint32_t* a, const uint32_t* b) {
    asm volatile(
        "mma.sync.aligned.m16n8k16.row.col.f32.bf16.bf16.f32 "
        "{%0,%1,%2,%3}, {%4,%5,%6,%7}, {%8,%9}, {%0,%1,%2,%3};"
        : "+f"(d[0]), "+f"(d[1]), "+f"(d[2]), "+f"(d[3])
        : "r"(a[0]), "r"(a[1]), "r"(a[2]), "r"(a[3]), "r"(b[0]), "r"(b[1]));
}
__device__ __forceinline__ uint32_t lds32(uint32_t a) {
    uint32_t v;
    asm volatile("ld.shared.u32 %0, [%1];" : "=r"(v) : "r"(a));
    return v;
}
// fp32 -> bf16 hi + rounded residual lo
__device__ __forceinline__ void split_bf16(float f, uint32_t& h, uint32_t& l) {
    const uint32_t bits = __float_as_uint(f);
    h = bits >> 16;
    const float lof = f - __uint_as_float(bits & 0xFFFF0000u);
    uint16_t lb;
    asm("cvt.rn.bf16.f32 %0, %1;" : "=h"(lb) : "f"(lof));
    l = lb;
}

// ---------------- profiling shim ---------------------------------------------
__global__ void dummy_kernel(float* __restrict__ d) {
    if (threadIdx.x == 0) d[blockIdx.x] = 0.f;
}

// ===================== split-bf16 kv conv1x1 body (mma.sync) =================
// D(128ch x 128pix) = W(128x256) @ X(256 x 128pix), K in 8 chunks of 32.
// Smem stage: Ahi[128][40]b16 | Alo | B2hi[16kp][136]u32 | B2lo  (dbl buffered)
#define KV_A_LO   10240
#define KV_B_HI   20480
#define KV_B_PIT  544          // 136 u32 per kp row (136 mod 32 == 8)
#define KV_STAGE  37888
#define KV_SMEM   (2 * KV_STAGE)

__device__ __forceinline__ void kv_body(
    char* smem, int b, int n0,
    const float* __restrict__ x,
    const unsigned* __restrict__ WhiP, const unsigned* __restrict__ WloP,
    float* __restrict__ kv, float* __restrict__ kv_pre)
{
    const uint32_t sbase = (uint32_t)__cvta_generic_to_shared(smem);
    const int tid  = threadIdx.x;
    const int lane = tid & 31;
    const int wid  = tid >> 5;
    const int wm0  = (wid >> 2) * 64;
    const int wn0  = (wid & 3) * 32;
    const float* Xb = x + (size_t)b * 256 * NPIX + n0;

    float acc[4][4][4];
#pragma unroll
    for (int i = 0; i < 4; i++)
#pragma unroll
        for (int j = 0; j < 4; j++)
#pragma unroll
            for (int r = 0; r < 4; r++) acc[i][j][r] = 0.f;

    auto cpA = [&](int c, int buf) {
#pragma unroll
        for (int i = 0; i < 4; i++) {
            const int e = tid + i * 256;
            const int mat = e >> 9, r = e & 511, m = r >> 2, q = r & 3;
            const uint32_t dst = sbase + buf * KV_STAGE + mat * KV_A_LO + m * 80 + q * 16;
            const char* src = (const char*)(mat ? WloP : WhiP) + m * 512 + c * 64 + q * 16;
            cp16(dst, src);
        }
        cp_commit();
    };

    float R[16];
#pragma unroll
    for (int i = 0; i < 2; i++) {
        const int e = tid + i * 256;
        const int kp = e >> 5, n4 = e & 31;
        const float4 r0 = *(const float4*)(Xb + (size_t)(2 * kp) * NPIX + n4 * 4);
        const float4 r1 = *(const float4*)(Xb + (size_t)(2 * kp + 1) * NPIX + n4 * 4);
        R[i * 8 + 0] = r0.x; R[i * 8 + 1] = r0.y; R[i * 8 + 2] = r0.z; R[i * 8 + 3] = r0.w;
        R[i * 8 + 4] = r1.x; R[i * 8 + 5] = r1.y; R[i * 8 + 6] = r1.z; R[i * 8 + 7] = r1.w;
    }
    cpA(0, 0);

    for (int c = 0; c < 8; c++) {
        const int buf = c & 1;
        const uint32_t stg = sbase + buf * KV_STAGE;

#pragma unroll
        for (int i = 0; i < 2; i++) {
            const int e = tid + i * 256;
            const int kp = e >> 5, n4 = e & 31;
            uint32_t h0[4], l0[4], h1[4], l1[4];
#pragma unroll
            for (int j = 0; j < 4; j++) {
                split_bf16(R[i * 8 + j],     h0[j], l0[j]);
                split_bf16(R[i * 8 + 4 + j], h1[j], l1[j]);
            }
            uint32_t hp[4], lp[4];
#pragma unroll
            for (int j = 0; j < 4; j++) {
                hp[j] = h0[j] | (h1[j] << 16);
                lp[j] = l0[j] | (l1[j] << 16);
            }
            const uint32_t addr = stg + KV_B_HI + (uint32_t)(kp * KV_B_PIT + n4 * 16);
            asm volatile("st.shared.v4.u32 [%0], {%1,%2,%3,%4};"
                         :: "r"(addr), "r"(hp[0]), "r"(hp[1]), "r"(hp[2]), "r"(hp[3]));
            asm volatile("st.shared.v4.u32 [%0+8704], {%1,%2,%3,%4};"
                         :: "r"(addr), "r"(lp[0]), "r"(lp[1]), "r"(lp[2]), "r"(lp[3]));
        }

        if (c < 7) {
#pragma unroll
            for (int i = 0; i < 2; i++) {
                const int e = tid + i * 256;
                const int kp = e >> 5, n4 = e & 31;
                const int k0 = (c + 1) * 32 + 2 * kp;
                const float4 r0 = *(const float4*)(Xb + (size_t)k0 * NPIX + n4 * 4);
                const float4 r1 = *(const float4*)(Xb + (size_t)(k0 + 1) * NPIX + n4 * 4);
                R[i * 8 + 0] = r0.x; R[i * 8 + 1] = r0.y;
                R[i * 8 + 2] = r0.z; R[i * 8 + 3] = r0.w;
                R[i * 8 + 4] = r1.x; R[i * 8 + 5] = r1.y;
                R[i * 8 + 6] = r1.z; R[i * 8 + 7] = r1.w;
            }
        }

        cp_wait<0>();
        __syncthreads();
        if (c < 7) cpA(c + 1, buf ^ 1);

#pragma unroll
        for (int ks2 = 0; ks2 < 16; ks2 += 8) {
            uint32_t bh[4][2], bl[4][2];
#pragma unroll
            for (int nt = 0; nt < 4; nt++) {
                const uint32_t bb = stg + KV_B_HI
                    + (uint32_t)((ks2 + (lane & 3)) * KV_B_PIT
                                 + (wn0 + nt * 8 + (lane >> 2)) * 4);
                bh[nt][0] = lds32(bb);
                bh[nt][1] = lds32(bb + 4 * KV_B_PIT);
                bl[nt][0] = lds32(bb + 8704);
                bl[nt][1] = lds32(bb + 8704 + 4 * KV_B_PIT);
            }
#pragma unroll
            for (int mt = 0; mt < 4; mt++) {
                const uint32_t aa = stg
                    + (uint32_t)((wm0 + mt * 16 + (lane >> 2)) * 80
                                 + (2 * ks2 + (lane & 3) * 2) * 2);
                uint32_t ah[4], al[4];
                ah[0] = lds32(aa);        ah[1] = lds32(aa + 640);
                ah[2] = lds32(aa + 16);   ah[3] = lds32(aa + 656);
                al[0] = lds32(aa + KV_A_LO);       al[1] = lds32(aa + KV_A_LO + 640);
                al[2] = lds32(aa + KV_A_LO + 16);  al[3] = lds32(aa + KV_A_LO + 656);
#pragma unroll
                for (int nt = 0; nt < 4; nt++) {
                    mma_bf16(acc[mt][nt], ah, bh[nt]);
                    mma_bf16(acc[mt][nt], ah, bl[nt]);
                    mma_bf16(acc[mt][nt], al, bh[nt]);
                }
            }
        }
    }

#pragma unroll
    for (int mt = 0; mt < 4; mt++) {
#pragma unroll
        for (int half = 0; half < 2; half++) {
            const int m = wm0 + mt * 16 + half * 8 + (lane >> 2);
            float* dst = (m < 32)
                ? kv     + (size_t)(b * 128 + m)      * NPIX
                : kv_pre + (size_t)(b * 96  + m - 32) * NPIX;
#pragma unroll
            for (int nt = 0; nt < 4; nt++) {
                const int n = n0 + wn0 + nt * 8 + (lane & 3) * 2;
                *(float2*)(dst + n) = make_float2(acc[mt][nt][half * 2],
                                                  acc[mt][nt][half * 2 + 1]);
            }
        }
    }
}

// ------------- fp32 conv1x1 body (256 threads, dyn smem, BN=128) -------------
template<int BM, int TM, int TN, int SPLITM>
__device__ __forceinline__ void gemm_body(
    char* smem, int n0,
    const float* __restrict__ Wt, const float* __restrict__ Xb,
    float* __restrict__ Y1, float* __restrict__ Y2, int C, int O)
{
    constexpr int BN = 128, BK = 16;
    constexpr int TX = BN / TN;
    constexpr int TY = BM / TM;
    constexpr int THREADS = TX * TY;
    static_assert(THREADS == 256, "bad tile");
    constexpr int A4 = BK * BM / 4;
    constexpr int B4 = BK * BN / 4;

    float* As = (float*)smem;
    float* Bs = (float*)(smem + 2 * BK * BM * 4);
    const uint32_t sA = (uint32_t)__cvta_generic_to_shared(smem);
    const uint32_t sB = sA + 2 * BK * BM * 4;

    const int tid = threadIdx.x;
    const int tx  = tid % TX;
    const int ty  = tid / TX;

    unsigned long long acc[TM][TN / 2];
#pragma unroll
    for (int i = 0; i < TM; i++)
#pragma unroll
        for (int j = 0; j < TN / 2; j++) acc[i][j] = 0ull;

    const int nIter = C / BK;

    auto prefetch = [&](int it, int buf) {
        const int k0 = it * BK;
#pragma unroll
        for (int e = tid; e < A4; e += THREADS) {
            int kk = e / (BM / 4), m4 = e % (BM / 4);
            cp16(sA + (uint32_t)(((buf * BK + kk) * BM + m4 * 4) * 4),
                 Wt + (size_t)(k0 + kk) * O + m4 * 4);
        }
#pragma unroll
        for (int e = tid; e < B4; e += THREADS) {
            int kk = e / (BN / 4), n4 = e % (BN / 4);
            cp16(sB + (uint32_t)(((buf * BK + kk) * BN + n4 * 4) * 4),
                 Xb + (size_t)(k0 + kk) * NPIX + n0 + n4 * 4);
        }
        cp_commit();
    };

    prefetch(0, 0);

    for (int it = 0; it < nIter; ++it) {
        const int buf = it & 1;
        if (it + 1 < nIter) {
            prefetch(it + 1, buf ^ 1);
            cp_wait<1>();
        } else {
            cp_wait<0>();
        }
        __syncthreads();

#pragma unroll
        for (int k = 0; k < BK; k++) {
            unsigned long long a2[TM], b2[TN / 2];
#pragma unroll
            for (int i = 0; i < TM; i++)
                a2[i] = pack2(As[(buf * BK + k) * BM + ty * TM + i]);
#pragma unroll
            for (int j4 = 0; j4 < TN / 4; j4++) {
                ulonglong2 bv = *(const ulonglong2*)(&Bs[(buf * BK + k) * BN + tx * TN + j4 * 4]);
                b2[j4 * 2 + 0] = bv.x;
                b2[j4 * 2 + 1] = bv.y;
            }
#pragma unroll
            for (int i = 0; i < TM; i++)
#pragma unroll
                for (int j = 0; j < TN / 2; j++)
                    fma2(acc[i][j], a2[i], b2[j]);
        }
        __syncthreads();
    }

#pragma unroll
    for (int i = 0; i < TM; i++) {
        float out[TN];
#pragma unroll
        for (int j = 0; j < TN / 2; j++) {
            float2 f = unpack2(acc[i][j]);
            out[2 * j] = f.x;
            out[2 * j + 1] = f.y;
        }
        const int m = ty * TM + i;
        float* dst = (m < SPLITM)
            ? Y1 + (size_t)m * NPIX + n0 + tx * TN
            : Y2 + (size_t)(m - SPLITM) * NPIX + n0 + tx * TN;
        float4* d4 = reinterpret_cast<float4*>(dst);
#pragma unroll
        for (int j4 = 0; j4 < TN / 4; j4++)
            d4[j4] = make_float4(out[4 * j4], out[4 * j4 + 1],
                                 out[4 * j4 + 2], out[4 * j4 + 3]);
    }
}

// ========== merged launch: kv tensor tiles + qh/ql fp32 tiles ================
__global__ void __launch_bounds__(256, 2)
mega_kernel(const float* __restrict__ x,
            const unsigned* __restrict__ WhiP, const unsigned* __restrict__ WloP,
            float* __restrict__ kv, float* __restrict__ kv_pre,
            const float* __restrict__ x_h, const float* __restrict__ WtQH,
            float* __restrict__ qh, float* __restrict__ qh_pre,
            const float* __restrict__ x_l, const float* __restrict__ WtQL,
            float* __restrict__ ql, float* __restrict__ ql_pre)
{
    extern __shared__ char smem[];
    const int bid = blockIdx.x;
    if (bid < 1024) {
        kv_body(smem, bid >> 9, (bid & 511) * 128, x, WhiP, WloP, kv, kv_pre);
    } else if (bid < 2048) {
        const int e = bid - 1024, b = e >> 9, n0 = (e & 511) * 128;
        gemm_body<32, 4, 4, 8>(smem, n0, WtQH, x_h + (size_t)b * 128 * NPIX,
                               qh + (size_t)b * 32 * NPIX,
                               qh_pre + (size_t)b * 24 * NPIX, 128, 32);
    } else {
        const int e = bid - 2048, b = e >> 9, n0 = (e & 511) * 128;
        gemm_body<16, 2, 4, 4>(smem, n0, WtQL, x_l + (size_t)b * 64 * NPIX,
                               ql + (size_t)b * 16 * NPIX,
                               ql_pre + (size_t)b * 12 * NPIX, 64, 16);
    }
}

// ========== split-bf16 final GEMM via mma.sync: out(192 x N) = Mc @ v ========
#define FG_A_LO  27648
#define FG_B_HI  55296
#define FG_B_PIT 544
#define FG_SMEM  90112

__global__ void __launch_bounds__(384, 2)
fin_mma_kernel(const float* __restrict__ kv,
               const unsigned* __restrict__ McHi, const unsigned* __restrict__ McLo,
               float* __restrict__ outh, float* __restrict__ outl)
{
    extern __shared__ char smem[];
    const uint32_t sbase = (uint32_t)__cvta_generic_to_shared(smem);
    const int tid  = threadIdx.x;
    const int lane = tid & 31;
    const int wid  = tid >> 5;
    const int b    = blockIdx.y;
    const int n0   = blockIdx.x * 128;
    const float* Vb = kv + (size_t)(b * 128 + 64) * NPIX + n0;

#pragma unroll
    for (int i = 0; i < 9; i++) {
        const int e = tid + i * 384;
        const int mat = e / 1728, r2 = e % 1728, row = r2 / 9, q = r2 % 9;
        const uint32_t dst = sbase + mat * FG_A_LO + row * 144 + q * 16;
        const unsigned* src = (mat ? McLo : McHi) + (size_t)(b * 192 + row) * 36 + q * 4;
        cp16(dst, src);
    }
    cp_commit();

    for (int e = tid; e < 1024; e += 384) {
        const int kp = e >> 5, n4 = e & 31;
        const float4 r0 = *(const float4*)(Vb + (size_t)(2 * kp) * NPIX + n4 * 4);
        const float4 r1 = *(const float4*)(Vb + (size_t)(2 * kp + 1) * NPIX + n4 * 4);
        const float v0[4] = {r0.x, r0.y, r0.z, r0.w};
        const float v1[4] = {r1.x, r1.y, r1.z, r1.w};
        uint32_t hp[4], lp[4];
#pragma unroll
        for (int j = 0; j < 4; j++) {
            uint32_t h0, l0, h1, l1;
            split_bf16(v0[j], h0, l0);
            split_bf16(v1[j], h1, l1);
            hp[j] = h0 | (h1 << 16);
            lp[j] = l0 | (l1 << 16);
        }
        const uint32_t addr = sbase + FG_B_HI + (uint32_t)(kp * FG_B_PIT + n4 * 16);
        asm volatile("st.shared.v4.u32 [%0], {%1,%2,%3,%4};"
                     :: "r"(addr), "r"(hp[0]), "r"(hp[1]), "r"(hp[2]), "r"(hp[3]));
        asm volatile("st.shared.v4.u32 [%0+17408], {%1,%2,%3,%4};"
                     :: "r"(addr), "r"(lp[0]), "r"(lp[1]), "r"(lp[2]), "r"(lp[3]));
    }
    cp_wait<0>();
    __syncthreads();

    const int m0 = wid * 16;
#pragma unroll
    for (int half = 0; half < 2; half++) {
        float acc[8][4];
#pragma unroll
        for (int j = 0; j < 8; j++)
#pragma unroll
            for (int r = 0; r < 4; r++) acc[j][r] = 0.f;

#pragma unroll
        for (int ks2 = 0; ks2 < 32; ks2 += 8) {
            const uint32_t aa = sbase
                + (uint32_t)((m0 + (lane >> 2)) * 144 + (2 * ks2 + (lane & 3) * 2) * 2);
            uint32_t ah[4], al[4];
            ah[0] = lds32(aa);        ah[1] = lds32(aa + 1152);
            ah[2] = lds32(aa + 16);   ah[3] = lds32(aa + 1168);
            al[0] = lds32(aa + FG_A_LO);        al[1] = lds32(aa + FG_A_LO + 1152);
            al[2] = lds32(aa + FG_A_LO + 16);   al[3] = lds32(aa + FG_A_LO + 1168);
#pragma unroll
            for (int g = 0; g < 2; g++) {
                uint32_t bh[4][2], bl[4][2];
#pragma unroll
                for (int nt = 0; nt < 4; nt++) {
                    const uint32_t bb = sbase + FG_B_HI
                        + (uint32_t)((ks2 + (lane & 3)) * FG_B_PIT
                                     + (half * 64 + g * 32 + nt * 8 + (lane >> 2)) * 4);
                    bh[nt][0] = lds32(bb);
                    bh[nt][1] = lds32(bb + 4 * FG_B_PIT);
                    bl[nt][0] = lds32(bb + 17408);
                    bl[nt][1] = lds32(bb + 17408 + 4 * FG_B_PIT);
                }
#pragma unroll
                for (int nt = 0; nt < 4; nt++) {
                    mma_bf16(acc[g * 4 + nt], ah, bh[nt]);
                    mma_bf16(acc[g * 4 + nt], ah, bl[nt]);
                    mma_bf16(acc[g * 4 + nt], al, bh[nt]);
                }
            }
        }

#pragma unroll
        for (int hrow = 0; hrow < 2; hrow++) {
            const int m = m0 + hrow * 8 + (lane >> 2);
            float* dst = (m < 128)
                ? outh + (size_t)(b * 128 + m) * NPIX
                : outl + (size_t)(b * 64 + m - 128) * NPIX;
#pragma unroll
            for (int nt = 0; nt < 8; nt++) {
                const int n = n0 + half * 64 + nt * 8 + (lane & 3) * 2;
                *(float2*)(dst + n) = make_float2(acc[nt][hrow * 2],
                                                  acc[nt][hrow * 2 + 1]);
            }
        }
    }
}

// -------- prep: pack w_kv into bf16 hi/lo pairs + transpose qh/ql weights ---
__global__ void prep_kernel(const float* __restrict__ w_kv,
                            const float* __restrict__ w_qh,
                            const float* __restrict__ w_ql,
                            unsigned* __restrict__ WhiP, unsigned* __restrict__ WloP,
                            float* __restrict__ WtQH, float* __restrict__ WtQL)
{
    int idx = blockIdx.x * 256 + threadIdx.x;
    if (idx < 16384) {
        int m = idx >> 7, i = idx & 127;
        uint32_t h0, l0, h1, l1;
        split_bf16(w_kv[m * 256 + 2 * i], h0, l0);
        split_bf16(w_kv[m * 256 + 2 * i + 1], h1, l1);
        WhiP[idx] = h0 | (h1 << 16);
        WloP[idx] = l0 | (l1 << 16);
    } else if (idx < 16384 + 4096) {
        int r = idx - 16384;
        int o = r / 128, c = r % 128;
        WtQH[c * 32 + o] = w_qh[r];
    } else if (idx < 16384 + 4096 + 1024) {
        int r = idx - 16384 - 4096;
        int o = r / 64, c = r % 64;
        WtQL[c * 16 + o] = w_ql[r];
    }
}

// ---- pyramid depthwise convs: per-row blocks, reflect ALU only at edges ----
// grid (256, 1, 264), 256 threads; y = blockIdx.x (uniform per block), x = tid
__global__ void pyramid_all_kernel(const float* __restrict__ kv_pre, float* __restrict__ kv,
                                   const float* __restrict__ qh_pre, float* __restrict__ qh,
                                   const float* __restrict__ ql_pre, float* __restrict__ ql,
                                   const float* __restrict__ kv1, const float* __restrict__ kv2,
                                   const float* __restrict__ kv3,
                                   const float* __restrict__ qh1, const float* __restrict__ qh2,
                                   const float* __restrict__ qh3,
                                   const float* __restrict__ ql1, const float* __restrict__ ql2,
                                   const float* __restrict__ ql3)
{
    int z = blockIdx.z;
    const float* in; float* out; int d;
    const float* W;
    if (z < 192) {
        int b = z / 96, c = z % 96;
        d = 1 + c / 32;
        in  = kv_pre + (size_t)(b * 96 + c) * NPIX;
        out = kv + (size_t)(b * 128 + 32 + c) * NPIX;
        W = (d == 1 ? kv1 : d == 2 ? kv2 : kv3) + (c % 32) * 9;
    } else if (z < 240) {
        int i = z - 192, b = i / 24, c = i % 24;
        d = 1 + c / 8;
        in  = qh_pre + (size_t)(b * 24 + c) * NPIX;
        out = qh + (size_t)(b * 32 + 8 + c) * NPIX;
        W = (d == 1 ? qh1 : d == 2 ? qh2 : qh3) + (c % 8) * 9;
    } else {
        int i = z - 240, b = i / 12, c = i % 12;
        d = 1 + c / 4;
        in  = ql_pre + (size_t)(b * 12 + c) * NPIX;
        out = ql + (size_t)(b * 16 + 4 + c) * NPIX;
        W = (d == 1 ? ql1 : d == 2 ? ql2 : ql3) + (c % 4) * 9;
    }

    float w[9];
#pragma unroll
    for (int i = 0; i < 9; i++) w[i] = W[i];

    const int y = blockIdx.x;          // one row per block
    const int x = threadIdx.x;

    // y reflection once per block (uniform)
    int ym = y - d; ym = ym < 0 ? -ym : ym;
    int yp = y + d; yp = yp > HW - 1 ? 2 * HW - 2 - yp : yp;
    const float* r0 = in + ym * HW;
    const float* r1 = in + y  * HW;
    const float* r2 = in + yp * HW;

    float s = 0.f;
    if (x >= d && x <= HW - 1 - d) {
        // interior: no x reflection (>= 250/256 threads)
        const int xm = x - d, xp = x + d;
        s = fmaf(w[0], r0[xm], s); s = fmaf(w[1], r0[x], s); s = fmaf(w[2], r0[xp], s);
        s = fmaf(w[3], r1[xm], s); s = fmaf(w[4], r1[x], s); s = fmaf(w[5], r1[xp], s);
        s = fmaf(w[6], r2[xm], s); s = fmaf(w[7], r2[x], s); s = fmaf(w[8], r2[xp], s);
    } else {
        int xm = x - d; xm = xm < 0 ? -xm : xm;
        int xp = x + d; xp = xp > HW - 1 ? 2 * HW - 2 - xp : xp;
        s = fmaf(w[0], r0[xm], s); s = fmaf(w[1], r0[x], s); s = fmaf(w[2], r0[xp], s);
        s = fmaf(w[3], r1[xm], s); s = fmaf(w[4], r1[x], s); s = fmaf(w[5], r1[xp], s);
        s = fmaf(w[6], r2[xm], s); s = fmaf(w[7], r2[x], s); s = fmaf(w[8], r2[xp], s);
    }
    out[y * HW + x] = s;
}

// ------- fused Gram + sum-of-squares: barrier-free, L2-shared k reads --------
__global__ void __launch_bounds__(128, 4)
gram_ss_kernel(const float* __restrict__ qh, const float* __restrict__ ql,
               const float* __restrict__ kv,
               float* __restrict__ Gpart, float* __restrict__ SSpart)
{
    const int grp   = blockIdx.x % 3;
    const int bh    = (blockIdx.x / 3) & 7;
    const int slice = blockIdx.x / 24;
    const int b = bh >> 2, head = bh & 3;
    const int tid  = threadIdx.x;
    const int lane = tid & 31;
    const int wid  = tid >> 5;
    const int nbase = slice * (NPIX / NSLICE);

    const float* kb = kv + (size_t)(b * 128 + head * 16) * NPIX;
    const float* qb = (grp == 0) ? qh + (size_t)(b * 32 + head * 8) * NPIX
                    : (grp == 1) ? qh + (size_t)(b * 32 + head * 8 + 4) * NPIX
                                 : ql + (size_t)(b * 16 + head * 4) * NPIX;

    float acc[4][16];
#pragma unroll
    for (int c = 0; c < 4; c++)
#pragma unroll
        for (int d = 0; d < 16; d++) acc[c][d] = 0.f;
    float qss[4] = {0.f, 0.f, 0.f, 0.f};
    float kss[16];
#pragma unroll
    for (int d = 0; d < 16; d++) kss[d] = 0.f;

#pragma unroll
    for (int t0 = 0; t0 < NPIX / NSLICE; t0 += 128) {
        const int n = nbase + t0 + tid;
        float q[4];
#pragma unroll
        for (int c = 0; c < 4; c++) q[c] = qb[(size_t)c * NPIX + n];
        float kvv[16];
#pragma unroll
        for (int d = 0; d < 16; d++) kvv[d] = kb[(size_t)d * NPIX + n];

#pragma unroll
        for (int c = 0; c < 4; c++) qss[c] = fmaf(q[c], q[c], qss[c]);
        if (grp == 0) {
#pragma unroll
            for (int d = 0; d < 16; d++) kss[d] = fmaf(kvv[d], kvv[d], kss[d]);
        }
#pragma unroll
        for (int c = 0; c < 4; c++)
#pragma unroll
            for (int d = 0; d < 16; d++)
                acc[c][d] = fmaf(q[c], kvv[d], acc[c][d]);
    }

#pragma unroll
    for (int c = 0; c < 4; c++) {
#pragma unroll
        for (int d = 0; d < 16; d++)
#pragma unroll
            for (int o = 16; o; o >>= 1)
                acc[c][d] += __shfl_xor_sync(0xffffffffu, acc[c][d], o);
#pragma unroll
        for (int o = 16; o; o >>= 1)
            qss[c] += __shfl_xor_sync(0xffffffffu, qss[c], o);
    }
    if (grp == 0) {
#pragma unroll
        for (int d = 0; d < 16; d++)
#pragma unroll
            for (int o = 16; o; o >>= 1)
                kss[d] += __shfl_xor_sync(0xffffffffu, kss[d], o);
    }

    __shared__ float red[4][64];
    __shared__ float ssred[4][20];
    if (lane == 0) {
#pragma unroll
        for (int c = 0; c < 4; c++) {
#pragma unroll
            for (int d = 0; d < 16; d++) red[wid][c * 16 + d] = acc[c][d];
            ssred[wid][16 + c] = qss[c];
        }
        if (grp == 0)
#pragma unroll
            for (int d = 0; d < 16; d++) ssred[wid][d] = kss[d];
    }
    __syncthreads();

    if (tid < 64) {
        float s = 0.f;
#pragma unroll
        for (int w = 0; w < 4; w++) s += red[w][tid];
        Gpart[((size_t)(bh * 3 + grp) * NSLICE + slice) * 64 + tid] = s;
    } else if (tid < 68) {
        const int c = tid - 64;
        float s = 0.f;
#pragma unroll
        for (int w = 0; w < 4; w++) s += ssred[w][16 + c];
        SSpart[((size_t)bh * NSLICE + slice) * 28 + 16 + grp * 4 + c] = s;
    } else if (tid < 84 && grp == 0) {
        const int d = tid - 68;
        float s = 0.f;
#pragma unroll
        for (int w = 0; w < 4; w++) s += ssred[w][d];
        SSpart[((size_t)bh * NSLICE + slice) * 28 + d] = s;
    }
}

// ------- gram/ss reduce + softmax + fold projection (emit bf16 hi/lo) -------
__global__ void softmax_fold_kernel(const float* __restrict__ Gpart,
                                    const float* __restrict__ SSpart,
                                    const float* __restrict__ temp,
                                    const float* __restrict__ w_ph, const float* __restrict__ w_pl,
                                    unsigned* __restrict__ McHi, unsigned* __restrict__ McLo)
{
    __shared__ float Gh[1024];
    __shared__ float Gl[512];
    __shared__ float Ah[1024];
    __shared__ float Al[512];
    __shared__ float knS[128];
    int t = threadIdx.x;

    for (int idx = t; idx < 1536; idx += 256) {
        int bh = idx / 192, rem = idx % 192;
        int grp = rem / 64, cd = rem % 64;
        float s = 0.f;
        for (int sl = 0; sl < NSLICE; sl++)
            s += Gpart[((size_t)(bh * 3 + grp) * NSLICE + sl) * 64 + cd];
        int c = cd / 16, d = cd % 16;
        if (grp < 2) Gh[(bh * 8 + grp * 4 + c) * 16 + d] = s;
        else         Gl[(bh * 4 + c) * 16 + d] = s;
    }
    if (t < 128) {
        int bh = t >> 4, d = t & 15;
        float s = 0.f;
        for (int sl = 0; sl < NSLICE; sl++)
            s += SSpart[((size_t)bh * NSLICE + sl) * 28 + d];
        knS[t] = fmaxf(sqrtf(s), 1e-12f);
    }
    __syncthreads();

    if (t < 96) {
        int b = t / 48, rem = t % 48, head = rem / 12, c = rem % 12;
        int bh = b * 4 + head;
        const float* Grow;
        float* Arow;
        int qpos;
        if (c < 8) {
            qpos = 16 + c;
            Grow = Gh + (bh * 8 + c) * 16;
            Arow = Ah + (bh * 8 + c) * 16;
        } else {
            qpos = 24 + (c - 8);
            Grow = Gl + (bh * 4 + c - 8) * 16;
            Arow = Al + (bh * 4 + c - 8) * 16;
        }
        float nq = 0.f;
        for (int sl = 0; sl < NSLICE; sl++)
            nq += SSpart[((size_t)bh * NSLICE + sl) * 28 + qpos];
        float qn = fmaxf(sqrtf(nq), 1e-12f);
        float tp = temp[head];
        float sc[16];
        float mx = -1e30f;
#pragma unroll
        for (int d = 0; d < 16; d++) {
            sc[d] = Grow[d] / (qn * knS[bh * 16 + d]) * tp;
            mx = fmaxf(mx, sc[d]);
        }
        float sum = 0.f;
#pragma unroll
        for (int d = 0; d < 16; d++) { sc[d] = expf(sc[d] - mx); sum += sc[d]; }
        float inv = 1.f / sum;
#pragma unroll
        for (int d = 0; d < 16; d++) Arow[d] = sc[d] * inv;
    }
    __syncthreads();

    for (int idx = t; idx < 2 * 192 * 32; idx += 256) {
        int b = idx / (192 * 32), rr = idx % (192 * 32);
        int o = rr / 32, dp = rr % 32;
        float s[2];
#pragma unroll
        for (int e = 0; e < 2; e++) {
            int dfull = dp * 2 + e;
            int head = dfull >> 4, dd = dfull & 15;
            float v = 0.f;
            if (o < 128) {
#pragma unroll
                for (int cp = 0; cp < 8; cp++)
                    v += w_ph[o * 32 + head * 8 + cp] * Ah[((b * 4 + head) * 8 + cp) * 16 + dd];
            } else {
                int ol = o - 128;
#pragma unroll
                for (int cp = 0; cp < 4; cp++)
                    v += w_pl[ol * 16 + head * 4 + cp] * Al[((b * 4 + head) * 4 + cp) * 16 + dd];
            }
            s[e] = v;
        }
        uint32_t h0, l0, h1, l1;
        split_bf16(s[0], h0, l0);
        split_bf16(s[1], h1, l1);
        McHi[(size_t)(b * 192 + o) * 36 + dp] = h0 | (h1 << 16);
        McLo[(size_t)(b * 192 + o) * 36 + dp] = l0 | (l1 << 16);
    }
}

// ---------------- host launcher ---------------------------------------------
extern "C" void kernel_launch(void* const* d_in, const int* in_sizes, int n_in,
                              void* d_out, int out_size)
{
    const float* x      = (const float*)d_in[0];
    const float* x_h    = (const float*)d_in[1];
    const float* x_l    = (const float*)d_in[2];
    const float* w_kv   = (const float*)d_in[3];
    const float* kv_dw1 = (const float*)d_in[4];
    const float* kv_dw2 = (const float*)d_in[5];
    const float* kv_dw3 = (const float*)d_in[6];
    const float* w_qh   = (const float*)d_in[7];
    const float* qh_dw1 = (const float*)d_in[8];
    const float* qh_dw2 = (const float*)d_in[9];
    const float* qh_dw3 = (const float*)d_in[10];
    const float* w_ql   = (const float*)d_in[11];
    const float* ql_dw1 = (const float*)d_in[12];
    const float* ql_dw2 = (const float*)d_in[13];
    const float* ql_dw3 = (const float*)d_in[14];
    const float* w_ph   = (const float*)d_in[15];
    const float* w_pl   = (const float*)d_in[16];
    const float* temp   = (const float*)d_in[17];
    float* out = (float*)d_out;

    float *kv_pre, *kv, *qh_pre, *qh, *ql_pre, *ql, *Gpart, *SSpart, *dmy;
    float *WtQH, *WtQL;
    unsigned *WhiP, *WloP, *McHi, *McLo;
    cudaGetSymbolAddress((void**)&kv_pre, g_kv_pre);
    cudaGetSymbolAddress((void**)&kv,     g_kv);
    cudaGetSymbolAddress((void**)&qh_pre, g_qh_pre);
    cudaGetSymbolAddress((void**)&qh,     g_qh);
    cudaGetSymbolAddress((void**)&ql_pre, g_ql_pre);
    cudaGetSymbolAddress((void**)&ql,     g_ql);
    cudaGetSymbolAddress((void**)&Gpart,  g_Gpart);
    cudaGetSymbolAddress((void**)&SSpart, g_SSpart);
    cudaGetSymbolAddress((void**)&McHi,   g_McHi);
    cudaGetSymbolAddress((void**)&McLo,   g_McLo);
    cudaGetSymbolAddress((void**)&WhiP,   g_WhiP);
    cudaGetSymbolAddress((void**)&WloP,   g_WloP);
    cudaGetSymbolAddress((void**)&WtQH,   g_WtQH);
    cudaGetSymbolAddress((void**)&WtQL,   g_WtQL);
    cudaGetSymbolAddress((void**)&dmy,    g_dummy);

    cudaFuncSetAttribute(mega_kernel,
                         cudaFuncAttributeMaxDynamicSharedMemorySize, KV_SMEM);
    cudaFuncSetAttribute(fin_mma_kernel,
                         cudaFuncAttributeMaxDynamicSharedMemorySize, FG_SMEM);

    // weight prep: bf16 hi/lo packing for kv + transposes for qh/ql
    prep_kernel<<<84, 256>>>(w_kv, w_qh, w_ql, WhiP, WloP, WtQH, WtQL);

    // shim: keep profiler window (launch #4) on pyramid to verify the fix
    dummy_kernel<<<1, 32>>>(dmy);

    // merged launch: kv tensor GEMM + qh/ql fp32 GEMMs (bid-range mapping)
    mega_kernel<<<3072, 256, KV_SMEM>>>(x, WhiP, WloP, kv, kv_pre,
                                        x_h, WtQH, qh, qh_pre,
                                        x_l, WtQL, ql, ql_pre);

    // pyramid depthwise convs (per-row blocks, edge-only reflect ALU)
    pyramid_all_kernel<<<dim3(256, 1, 264), 256>>>(
        kv_pre, kv, qh_pre, qh, ql_pre, ql,
        kv_dw1, kv_dw2, kv_dw3, qh_dw1, qh_dw2, qh_dw3, ql_dw1, ql_dw2, ql_dw3);

    // fused Gram + sum-of-squares: barrier-free per-team blocks, L2-shared k
    gram_ss_kernel<<<24 * NSLICE, 128>>>(qh, ql, kv, Gpart, SSpart);

    // reduce + softmax + fold attention -> bf16 hi/lo projection matrix
    softmax_fold_kernel<<<1, 256>>>(Gpart, SSpart, temp, w_ph, w_pl, McHi, McLo);

    // final attention-apply + projection (k-pair-packed B, conflict-free)
    fin_mma_kernel<<<dim3(512, 2), 384, FG_SMEM>>>(
        kv, McHi, McLo, out, out + 2 * 128 * NPIX);
}

// round 17
// speedup vs baseline: 1.1141x; 1.1141x over previous
#include <cuda_runtime.h>
#include <cstdint>

#define NPIX 65536   // 256*256
#define HW   256
#define NSLICE 64

// ---------------- scratch (device globals; no allocation allowed) ----------
__device__ float g_kv_pre[2 * 96 * NPIX];   // dwconv-input channels only
__device__ float g_kv    [2 * 128 * NPIX];
__device__ float g_qh_pre[2 * 24 * NPIX];
__device__ float g_qh    [2 * 32 * NPIX];
__device__ float g_ql_pre[2 * 12 * NPIX];
__device__ float g_ql    [2 * 16 * NPIX];
__device__ float g_Gpart [8 * 3 * NSLICE * 64]; // [bh][grp][slice][c*16+d]
__device__ float g_SSpart[8 * NSLICE * 28];     // [bh][slice][k16|qh8|ql4]
__device__ unsigned g_McHi[2 * 192 * 36];  // folded proj hi bf16 pairs [b][o][kpair]
__device__ unsigned g_McLo[2 * 192 * 36];
__device__ unsigned g_WhiP[128 * 128];     // w_kv hi bf16, packed 2/k-pair
__device__ unsigned g_WloP[128 * 128];     // w_kv lo bf16
__device__ float g_WtQH  [128 * 32];
__device__ float g_WtQL  [64 * 16];
__device__ float g_dummy [32];

// ---------------- packed f32x2 helpers --------------------------------------
__device__ __forceinline__ unsigned long long pack2(float a) {
    unsigned long long r;
    asm("mov.b64 %0, {%1, %1};" : "=l"(r) : "f"(a));
    return r;
}
__device__ __forceinline__ void fma2(unsigned long long& d,
                                     unsigned long long a,
                                     unsigned long long b) {
    asm("fma.rn.f32x2 %0, %1, %2, %0;" : "+l"(d) : "l"(a), "l"(b));
}
__device__ __forceinline__ float2 unpack2(unsigned long long v) {
    float2 f;
    asm("mov.b64 {%0, %1}, %2;" : "=f"(f.x), "=f"(f.y) : "l"(v));
    return f;
}

// ---------------- cp.async helpers ------------------------------------------
__device__ __forceinline__ void cp16(uint32_t s, const void* g) {
    asm volatile("cp.async.cg.shared.global [%0], [%1], 16;" :: "r"(s), "l"(g));
}
__device__ __forceinline__ void cp_commit() {
    asm volatile("cp.async.commit_group;" ::: "memory");
}
template<int N>
__device__ __forceinline__ void cp_wait() {
    asm volatile("cp.async.wait_group %0;" :: "n"(N) : "memory");
}

// ---------------- mma.sync bf16 helpers --------------------------------------
__device__ __forceinline__ void mma_bf16(float* d, const uint32_t* a, const uint32_t* b) {
    asm volatile(
        "mma.sync.aligned.m16n8k16.row.col.f32.bf16.bf16.f32 "
        "{%0,%1,%2,%3}, {%4,%5,%6,%7}, {%8,%9}, {%0,%1,%2,%3};"
        : "+f"(d[0]), "+f"(d[1]), "+f"(d[2]), "+f"(d[3])
        : "r"(a[0]), "r"(a[1]), "r"(a[2]), "r"(a[3]), "r"(b[0]), "r"(b[1]));
}
__device__ __forceinline__ uint32_t lds32(uint32_t a) {
    uint32_t v;
    asm volatile("ld.shared.u32 %0, [%1];" : "=r"(v) : "r"(a));
    return v;
}
// fp32 -> bf16 hi + rounded residual lo
__device__ __forceinline__ void split_bf16(float f, uint32_t& h, uint32_t& l) {
    const uint32_t bits = __float_as_uint(f);
    h = bits >> 16;
    const float lof = f - __uint_as_float(bits & 0xFFFF0000u);
    uint16_t lb;
    asm("cvt.rn.bf16.f32 %0, %1;" : "=h"(lb) : "f"(lof));
    l = lb;
}

// ---------------- profiling shim ---------------------------------------------
__global__ void dummy_kernel(float* __restrict__ d) {
    if (threadIdx.x == 0) d[blockIdx.x] = 0.f;
}

// ===================== split-bf16 kv conv1x1 body (mma.sync) =================
#define KV_A_LO   10240
#define KV_B_HI   20480
#define KV_B_PIT  544
#define KV_STAGE  37888
#define KV_SMEM   (2 * KV_STAGE)

__device__ __forceinline__ void kv_body(
    char* smem, int b, int n0,
    const float* __restrict__ x,
    const unsigned* __restrict__ WhiP, const unsigned* __restrict__ WloP,
    float* __restrict__ kv, float* __restrict__ kv_pre)
{
    const uint32_t sbase = (uint32_t)__cvta_generic_to_shared(smem);
    const int tid  = threadIdx.x;
    const int lane = tid & 31;
    const int wid  = tid >> 5;
    const int wm0  = (wid >> 2) * 64;
    const int wn0  = (wid & 3) * 32;
    const float* Xb = x + (size_t)b * 256 * NPIX + n0;

    float acc[4][4][4];
#pragma unroll
    for (int i = 0; i < 4; i++)
#pragma unroll
        for (int j = 0; j < 4; j++)
#pragma unroll
            for (int r = 0; r < 4; r++) acc[i][j][r] = 0.f;

    auto cpA = [&](int c, int buf) {
#pragma unroll
        for (int i = 0; i < 4; i++) {
            const int e = tid + i * 256;
            const int mat = e >> 9, r = e & 511, m = r >> 2, q = r & 3;
            const uint32_t dst = sbase + buf * KV_STAGE + mat * KV_A_LO + m * 80 + q * 16;
            const char* src = (const char*)(mat ? WloP : WhiP) + m * 512 + c * 64 + q * 16;
            cp16(dst, src);
        }
        cp_commit();
    };

    float R[16];
#pragma unroll
    for (int i = 0; i < 2; i++) {
        const int e = tid + i * 256;
        const int kp = e >> 5, n4 = e & 31;
        const float4 r0 = *(const float4*)(Xb + (size_t)(2 * kp) * NPIX + n4 * 4);
        const float4 r1 = *(const float4*)(Xb + (size_t)(2 * kp + 1) * NPIX + n4 * 4);
        R[i * 8 + 0] = r0.x; R[i * 8 + 1] = r0.y; R[i * 8 + 2] = r0.z; R[i * 8 + 3] = r0.w;
        R[i * 8 + 4] = r1.x; R[i * 8 + 5] = r1.y; R[i * 8 + 6] = r1.z; R[i * 8 + 7] = r1.w;
    }
    cpA(0, 0);

    for (int c = 0; c < 8; c++) {
        const int buf = c & 1;
        const uint32_t stg = sbase + buf * KV_STAGE;

#pragma unroll
        for (int i = 0; i < 2; i++) {
            const int e = tid + i * 256;
            const int kp = e >> 5, n4 = e & 31;
            uint32_t h0[4], l0[4], h1[4], l1[4];
#pragma unroll
            for (int j = 0; j < 4; j++) {
                split_bf16(R[i * 8 + j],     h0[j], l0[j]);
                split_bf16(R[i * 8 + 4 + j], h1[j], l1[j]);
            }
            uint32_t hp[4], lp[4];
#pragma unroll
            for (int j = 0; j < 4; j++) {
                hp[j] = h0[j] | (h1[j] << 16);
                lp[j] = l0[j] | (l1[j] << 16);
            }
            const uint32_t addr = stg + KV_B_HI + (uint32_t)(kp * KV_B_PIT + n4 * 16);
            asm volatile("st.shared.v4.u32 [%0], {%1,%2,%3,%4};"
                         :: "r"(addr), "r"(hp[0]), "r"(hp[1]), "r"(hp[2]), "r"(hp[3]));
            asm volatile("st.shared.v4.u32 [%0+8704], {%1,%2,%3,%4};"
                         :: "r"(addr), "r"(lp[0]), "r"(lp[1]), "r"(lp[2]), "r"(lp[3]));
        }

        if (c < 7) {
#pragma unroll
            for (int i = 0; i < 2; i++) {
                const int e = tid + i * 256;
                const int kp = e >> 5, n4 = e & 31;
                const int k0 = (c + 1) * 32 + 2 * kp;
                const float4 r0 = *(const float4*)(Xb + (size_t)k0 * NPIX + n4 * 4);
                const float4 r1 = *(const float4*)(Xb + (size_t)(k0 + 1) * NPIX + n4 * 4);
                R[i * 8 + 0] = r0.x; R[i * 8 + 1] = r0.y;
                R[i * 8 + 2] = r0.z; R[i * 8 + 3] = r0.w;
                R[i * 8 + 4] = r1.x; R[i * 8 + 5] = r1.y;
                R[i * 8 + 6] = r1.z; R[i * 8 + 7] = r1.w;
            }
        }

        cp_wait<0>();
        __syncthreads();
        if (c < 7) cpA(c + 1, buf ^ 1);

#pragma unroll
        for (int ks2 = 0; ks2 < 16; ks2 += 8) {
            uint32_t bh[4][2], bl[4][2];
#pragma unroll
            for (int nt = 0; nt < 4; nt++) {
                const uint32_t bb = stg + KV_B_HI
                    + (uint32_t)((ks2 + (lane & 3)) * KV_B_PIT
                                 + (wn0 + nt * 8 + (lane >> 2)) * 4);
                bh[nt][0] = lds32(bb);
                bh[nt][1] = lds32(bb + 4 * KV_B_PIT);
                bl[nt][0] = lds32(bb + 8704);
                bl[nt][1] = lds32(bb + 8704 + 4 * KV_B_PIT);
            }
#pragma unroll
            for (int mt = 0; mt < 4; mt++) {
                const uint32_t aa = stg
                    + (uint32_t)((wm0 + mt * 16 + (lane >> 2)) * 80
                                 + (2 * ks2 + (lane & 3) * 2) * 2);
                uint32_t ah[4], al[4];
                ah[0] = lds32(aa);        ah[1] = lds32(aa + 640);
                ah[2] = lds32(aa + 16);   ah[3] = lds32(aa + 656);
                al[0] = lds32(aa + KV_A_LO);       al[1] = lds32(aa + KV_A_LO + 640);
                al[2] = lds32(aa + KV_A_LO + 16);  al[3] = lds32(aa + KV_A_LO + 656);
#pragma unroll
                for (int nt = 0; nt < 4; nt++) {
                    mma_bf16(acc[mt][nt], ah, bh[nt]);
                    mma_bf16(acc[mt][nt], ah, bl[nt]);
                    mma_bf16(acc[mt][nt], al, bh[nt]);
                }
            }
        }
    }

#pragma unroll
    for (int mt = 0; mt < 4; mt++) {
#pragma unroll
        for (int half = 0; half < 2; half++) {
            const int m = wm0 + mt * 16 + half * 8 + (lane >> 2);
            float* dst = (m < 32)
                ? kv     + (size_t)(b * 128 + m)      * NPIX
                : kv_pre + (size_t)(b * 96  + m - 32) * NPIX;
#pragma unroll
            for (int nt = 0; nt < 4; nt++) {
                const int n = n0 + wn0 + nt * 8 + (lane & 3) * 2;
                *(float2*)(dst + n) = make_float2(acc[mt][nt][half * 2],
                                                  acc[mt][nt][half * 2 + 1]);
            }
        }
    }
}

// ------------- fp32 conv1x1 body (256 threads, dyn smem, BN=128) -------------
template<int BM, int TM, int TN, int SPLITM>
__device__ __forceinline__ void gemm_body(
    char* smem, int n0,
    const float* __restrict__ Wt, const float* __restrict__ Xb,
    float* __restrict__ Y1, float* __restrict__ Y2, int C, int O)
{
    constexpr int BN = 128, BK = 16;
    constexpr int TX = BN / TN;
    constexpr int TY = BM / TM;
    constexpr int THREADS = TX * TY;
    static_assert(THREADS == 256, "bad tile");
    constexpr int A4 = BK * BM / 4;
    constexpr int B4 = BK * BN / 4;

    float* As = (float*)smem;
    float* Bs = (float*)(smem + 2 * BK * BM * 4);
    const uint32_t sA = (uint32_t)__cvta_generic_to_shared(smem);
    const uint32_t sB = sA + 2 * BK * BM * 4;

    const int tid = threadIdx.x;
    const int tx  = tid % TX;
    const int ty  = tid / TX;

    unsigned long long acc[TM][TN / 2];
#pragma unroll
    for (int i = 0; i < TM; i++)
#pragma unroll
        for (int j = 0; j < TN / 2; j++) acc[i][j] = 0ull;

    const int nIter = C / BK;

    auto prefetch = [&](int it, int buf) {
        const int k0 = it * BK;
#pragma unroll
        for (int e = tid; e < A4; e += THREADS) {
            int kk = e / (BM / 4), m4 = e % (BM / 4);
            cp16(sA + (uint32_t)(((buf * BK + kk) * BM + m4 * 4) * 4),
                 Wt + (size_t)(k0 + kk) * O + m4 * 4);
        }
#pragma unroll
        for (int e = tid; e < B4; e += THREADS) {
            int kk = e / (BN / 4), n4 = e % (BN / 4);
            cp16(sB + (uint32_t)(((buf * BK + kk) * BN + n4 * 4) * 4),
                 Xb + (size_t)(k0 + kk) * NPIX + n0 + n4 * 4);
        }
        cp_commit();
    };

    prefetch(0, 0);

    for (int it = 0; it < nIter; ++it) {
        const int buf = it & 1;
        if (it + 1 < nIter) {
            prefetch(it + 1, buf ^ 1);
            cp_wait<1>();
        } else {
            cp_wait<0>();
        }
        __syncthreads();

#pragma unroll
        for (int k = 0; k < BK; k++) {
            unsigned long long a2[TM], b2[TN / 2];
#pragma unroll
            for (int i = 0; i < TM; i++)
                a2[i] = pack2(As[(buf * BK + k) * BM + ty * TM + i]);
#pragma unroll
            for (int j4 = 0; j4 < TN / 4; j4++) {
                ulonglong2 bv = *(const ulonglong2*)(&Bs[(buf * BK + k) * BN + tx * TN + j4 * 4]);
                b2[j4 * 2 + 0] = bv.x;
                b2[j4 * 2 + 1] = bv.y;
            }
#pragma unroll
            for (int i = 0; i < TM; i++)
#pragma unroll
                for (int j = 0; j < TN / 2; j++)
                    fma2(acc[i][j], a2[i], b2[j]);
        }
        __syncthreads();
    }

#pragma unroll
    for (int i = 0; i < TM; i++) {
        float out[TN];
#pragma unroll
        for (int j = 0; j < TN / 2; j++) {
            float2 f = unpack2(acc[i][j]);
            out[2 * j] = f.x;
            out[2 * j + 1] = f.y;
        }
        const int m = ty * TM + i;
        float* dst = (m < SPLITM)
            ? Y1 + (size_t)m * NPIX + n0 + tx * TN
            : Y2 + (size_t)(m - SPLITM) * NPIX + n0 + tx * TN;
        float4* d4 = reinterpret_cast<float4*>(dst);
#pragma unroll
        for (int j4 = 0; j4 < TN / 4; j4++)
            d4[j4] = make_float4(out[4 * j4], out[4 * j4 + 1],
                                 out[4 * j4 + 2], out[4 * j4 + 3]);
    }
}

// ========== merged launch: kv tensor tiles + qh/ql fp32 tiles ================
__global__ void __launch_bounds__(256, 2)
mega_kernel(const float* __restrict__ x,
            const unsigned* __restrict__ WhiP, const unsigned* __restrict__ WloP,
            float* __restrict__ kv, float* __restrict__ kv_pre,
            const float* __restrict__ x_h, const float* __restrict__ WtQH,
            float* __restrict__ qh, float* __restrict__ qh_pre,
            const float* __restrict__ x_l, const float* __restrict__ WtQL,
            float* __restrict__ ql, float* __restrict__ ql_pre)
{
    extern __shared__ char smem[];
    const int bid = blockIdx.x;
    if (bid < 1024) {
        kv_body(smem, bid >> 9, (bid & 511) * 128, x, WhiP, WloP, kv, kv_pre);
    } else if (bid < 2048) {
        const int e = bid - 1024, b = e >> 9, n0 = (e & 511) * 128;
        gemm_body<32, 4, 4, 8>(smem, n0, WtQH, x_h + (size_t)b * 128 * NPIX,
                               qh + (size_t)b * 32 * NPIX,
                               qh_pre + (size_t)b * 24 * NPIX, 128, 32);
    } else {
        const int e = bid - 2048, b = e >> 9, n0 = (e & 511) * 128;
        gemm_body<16, 2, 4, 4>(smem, n0, WtQL, x_l + (size_t)b * 64 * NPIX,
                               ql + (size_t)b * 16 * NPIX,
                               ql_pre + (size_t)b * 12 * NPIX, 64, 16);
    }
}

// ========== split-bf16 final GEMM via mma.sync: out(192 x N) = Mc @ v ========
#define FG_A_LO  27648
#define FG_B_HI  55296
#define FG_B_PIT 544
#define FG_SMEM  90112

__global__ void __launch_bounds__(384, 2)
fin_mma_kernel(const float* __restrict__ kv,
               const unsigned* __restrict__ McHi, const unsigned* __restrict__ McLo,
               float* __restrict__ outh, float* __restrict__ outl)
{
    extern __shared__ char smem[];
    const uint32_t sbase = (uint32_t)__cvta_generic_to_shared(smem);
    const int tid  = threadIdx.x;
    const int lane = tid & 31;
    const int wid  = tid >> 5;
    const int b    = blockIdx.y;
    const int n0   = blockIdx.x * 128;
    const float* Vb = kv + (size_t)(b * 128 + 64) * NPIX + n0;

#pragma unroll
    for (int i = 0; i < 9; i++) {
        const int e = tid + i * 384;
        const int mat = e / 1728, r2 = e % 1728, row = r2 / 9, q = r2 % 9;
        const uint32_t dst = sbase + mat * FG_A_LO + row * 144 + q * 16;
        const unsigned* src = (mat ? McLo : McHi) + (size_t)(b * 192 + row) * 36 + q * 4;
        cp16(dst, src);
    }
    cp_commit();

    for (int e = tid; e < 1024; e += 384) {
        const int kp = e >> 5, n4 = e & 31;
        const float4 r0 = *(const float4*)(Vb + (size_t)(2 * kp) * NPIX + n4 * 4);
        const float4 r1 = *(const float4*)(Vb + (size_t)(2 * kp + 1) * NPIX + n4 * 4);
        const float v0[4] = {r0.x, r0.y, r0.z, r0.w};
        const float v1[4] = {r1.x, r1.y, r1.z, r1.w};
        uint32_t hp[4], lp[4];
#pragma unroll
        for (int j = 0; j < 4; j++) {
            uint32_t h0, l0, h1, l1;
            split_bf16(v0[j], h0, l0);
            split_bf16(v1[j], h1, l1);
            hp[j] = h0 | (h1 << 16);
            lp[j] = l0 | (l1 << 16);
        }
        const uint32_t addr = sbase + FG_B_HI + (uint32_t)(kp * FG_B_PIT + n4 * 16);
        asm volatile("st.shared.v4.u32 [%0], {%1,%2,%3,%4};"
                     :: "r"(addr), "r"(hp[0]), "r"(hp[1]), "r"(hp[2]), "r"(hp[3]));
        asm volatile("st.shared.v4.u32 [%0+17408], {%1,%2,%3,%4};"
                     :: "r"(addr), "r"(lp[0]), "r"(lp[1]), "r"(lp[2]), "r"(lp[3]));
    }
    cp_wait<0>();
    __syncthreads();

    const int m0 = wid * 16;
#pragma unroll
    for (int half = 0; half < 2; half++) {
        float acc[8][4];
#pragma unroll
        for (int j = 0; j < 8; j++)
#pragma unroll
            for (int r = 0; r < 4; r++) acc[j][r] = 0.f;

#pragma unroll
        for (int ks2 = 0; ks2 < 32; ks2 += 8) {
            const uint32_t aa = sbase
                + (uint32_t)((m0 + (lane >> 2)) * 144 + (2 * ks2 + (lane & 3) * 2) * 2);
            uint32_t ah[4], al[4];
            ah[0] = lds32(aa);        ah[1] = lds32(aa + 1152);
            ah[2] = lds32(aa + 16);   ah[3] = lds32(aa + 1168);
            al[0] = lds32(aa + FG_A_LO);        al[1] = lds32(aa + FG_A_LO + 1152);
            al[2] = lds32(aa + FG_A_LO + 16);   al[3] = lds32(aa + FG_A_LO + 1168);
#pragma unroll
            for (int g = 0; g < 2; g++) {
                uint32_t bh[4][2], bl[4][2];
#pragma unroll
                for (int nt = 0; nt < 4; nt++) {
                    const uint32_t bb = sbase + FG_B_HI
                        + (uint32_t)((ks2 + (lane & 3)) * FG_B_PIT
                                     + (half * 64 + g * 32 + nt * 8 + (lane >> 2)) * 4);
                    bh[nt][0] = lds32(bb);
                    bh[nt][1] = lds32(bb + 4 * FG_B_PIT);
                    bl[nt][0] = lds32(bb + 17408);
                    bl[nt][1] = lds32(bb + 17408 + 4 * FG_B_PIT);
                }
#pragma unroll
                for (int nt = 0; nt < 4; nt++) {
                    mma_bf16(acc[g * 4 + nt], ah, bh[nt]);
                    mma_bf16(acc[g * 4 + nt], ah, bl[nt]);
                    mma_bf16(acc[g * 4 + nt], al, bh[nt]);
                }
            }
        }

#pragma unroll
        for (int hrow = 0; hrow < 2; hrow++) {
            const int m = m0 + hrow * 8 + (lane >> 2);
            float* dst = (m < 128)
                ? outh + (size_t)(b * 128 + m) * NPIX
                : outl + (size_t)(b * 64 + m - 128) * NPIX;
#pragma unroll
            for (int nt = 0; nt < 8; nt++) {
                const int n = n0 + half * 64 + nt * 8 + (lane & 3) * 2;
                *(float2*)(dst + n) = make_float2(acc[nt][hrow * 2],
                                                  acc[nt][hrow * 2 + 1]);
            }
        }
    }
}

// -------- prep: pack w_kv into bf16 hi/lo pairs + transpose qh/ql weights ---
__global__ void prep_kernel(const float* __restrict__ w_kv,
                            const float* __restrict__ w_qh,
                            const float* __restrict__ w_ql,
                            unsigned* __restrict__ WhiP, unsigned* __restrict__ WloP,
                            float* __restrict__ WtQH, float* __restrict__ WtQL)
{
    int idx = blockIdx.x * 256 + threadIdx.x;
    if (idx < 16384) {
        int m = idx >> 7, i = idx & 127;
        uint32_t h0, l0, h1, l1;
        split_bf16(w_kv[m * 256 + 2 * i], h0, l0);
        split_bf16(w_kv[m * 256 + 2 * i + 1], h1, l1);
        WhiP[idx] = h0 | (h1 << 16);
        WloP[idx] = l0 | (l1 << 16);
    } else if (idx < 16384 + 4096) {
        int r = idx - 16384;
        int o = r / 128, c = r % 128;
        WtQH[c * 32 + o] = w_qh[r];
    } else if (idx < 16384 + 4096 + 1024) {
        int r = idx - 16384 - 4096;
        int o = r / 64, c = r % 64;
        WtQL[c * 16 + o] = w_ql[r];
    }
}

// ---- pyramid depthwise convs: 4 px/thread via float4 windows ---------------
// grid (64, 1, 264), 256 threads: 4 rows x 64 threads; thread = 4 consec px.
// Tap order/values identical to reference -> bit-identical output.
template<int D>
__device__ __forceinline__ void conv4(const float* V0, const float* V1,
                                      const float* V2, const float* w,
                                      float* o)
{
#pragma unroll
    for (int px = 0; px < 4; px++) {
        float s = 0.f;
        s = fmaf(w[0], V0[4 + px - D], s);
        s = fmaf(w[1], V0[4 + px], s);
        s = fmaf(w[2], V0[4 + px + D], s);
        s = fmaf(w[3], V1[4 + px - D], s);
        s = fmaf(w[4], V1[4 + px], s);
        s = fmaf(w[5], V1[4 + px + D], s);
        s = fmaf(w[6], V2[4 + px - D], s);
        s = fmaf(w[7], V2[4 + px], s);
        s = fmaf(w[8], V2[4 + px + D], s);
        o[px] = s;
    }
}

__device__ __forceinline__ void load_win(const float* __restrict__ row,
                                         int x4, float* V)
{
    float4 bm, bc, bp;
    if (x4 == 0)
        bm = make_float4(row[4], row[3], row[2], row[1]);       // reflect -4..-1
    else
        bm = *(const float4*)(row + x4 - 4);
    bc = *(const float4*)(row + x4);
    if (x4 == HW - 4)
        bp = make_float4(row[254], row[253], row[252], row[251]); // reflect 256..259
    else
        bp = *(const float4*)(row + x4 + 4);
    V[0] = bm.x; V[1] = bm.y; V[2]  = bm.z; V[3]  = bm.w;
    V[4] = bc.x; V[5] = bc.y; V[6]  = bc.z; V[7]  = bc.w;
    V[8] = bp.x; V[9] = bp.y; V[10] = bp.z; V[11] = bp.w;
}

__global__ void pyramid_all_kernel(const float* __restrict__ kv_pre, float* __restrict__ kv,
                                   const float* __restrict__ qh_pre, float* __restrict__ qh,
                                   const float* __restrict__ ql_pre, float* __restrict__ ql,
                                   const float* __restrict__ kv1, const float* __restrict__ kv2,
                                   const float* __restrict__ kv3,
                                   const float* __restrict__ qh1, const float* __restrict__ qh2,
                                   const float* __restrict__ qh3,
                                   const float* __restrict__ ql1, const float* __restrict__ ql2,
                                   const float* __restrict__ ql3)
{
    int z = blockIdx.z;
    const float* in; float* out; int d;
    const float* W;
    if (z < 192) {
        int b = z / 96, c = z % 96;
        d = 1 + c / 32;
        in  = kv_pre + (size_t)(b * 96 + c) * NPIX;
        out = kv + (size_t)(b * 128 + 32 + c) * NPIX;
        W = (d == 1 ? kv1 : d == 2 ? kv2 : kv3) + (c % 32) * 9;
    } else if (z < 240) {
        int i = z - 192, b = i / 24, c = i % 24;
        d = 1 + c / 8;
        in  = qh_pre + (size_t)(b * 24 + c) * NPIX;
        out = qh + (size_t)(b * 32 + 8 + c) * NPIX;
        W = (d == 1 ? qh1 : d == 2 ? qh2 : qh3) + (c % 8) * 9;
    } else {
        int i = z - 240, b = i / 12, c = i % 12;
        d = 1 + c / 4;
        in  = ql_pre + (size_t)(b * 12 + c) * NPIX;
        out = ql + (size_t)(b * 16 + 4 + c) * NPIX;
        W = (d == 1 ? ql1 : d == 2 ? ql2 : ql3) + (c % 4) * 9;
    }

    float w[9];
#pragma unroll
    for (int i = 0; i < 9; i++) w[i] = W[i];

    const int y  = blockIdx.x * 4 + (threadIdx.x >> 6);  // warp-uniform
    const int x4 = (threadIdx.x & 63) * 4;

    int ym = y - d; ym = ym < 0 ? -ym : ym;
    int yp = y + d; yp = yp > HW - 1 ? 2 * HW - 2 - yp : yp;

    float V0[12], V1[12], V2[12];
    load_win(in + ym * HW, x4, V0);
    load_win(in + y  * HW, x4, V1);
    load_win(in + yp * HW, x4, V2);

    float o[4];
    if (d == 1)      conv4<1>(V0, V1, V2, w, o);
    else if (d == 2) conv4<2>(V0, V1, V2, w, o);
    else             conv4<3>(V0, V1, V2, w, o);

    *(float4*)(out + y * HW + x4) = make_float4(o[0], o[1], o[2], o[3]);
}

// ------- fused Gram + sum-of-squares: barrier-free, L2-shared k reads --------
__global__ void __launch_bounds__(128, 4)
gram_ss_kernel(const float* __restrict__ qh, const float* __restrict__ ql,
               const float* __restrict__ kv,
               float* __restrict__ Gpart, float* __restrict__ SSpart)
{
    const int grp   = blockIdx.x % 3;
    const int bh    = (blockIdx.x / 3) & 7;
    const int slice = blockIdx.x / 24;
    const int b = bh >> 2, head = bh & 3;
    const int tid  = threadIdx.x;
    const int lane = tid & 31;
    const int wid  = tid >> 5;
    const int nbase = slice * (NPIX / NSLICE);

    const float* kb = kv + (size_t)(b * 128 + head * 16) * NPIX;
    const float* qb = (grp == 0) ? qh + (size_t)(b * 32 + head * 8) * NPIX
                    : (grp == 1) ? qh + (size_t)(b * 32 + head * 8 + 4) * NPIX
                                 : ql + (size_t)(b * 16 + head * 4) * NPIX;

    float acc[4][16];
#pragma unroll
    for (int c = 0; c < 4; c++)
#pragma unroll
        for (int d = 0; d < 16; d++) acc[c][d] = 0.f;
    float qss[4] = {0.f, 0.f, 0.f, 0.f};
    float kss[16];
#pragma unroll
    for (int d = 0; d < 16; d++) kss[d] = 0.f;

#pragma unroll
    for (int t0 = 0; t0 < NPIX / NSLICE; t0 += 128) {
        const int n = nbase + t0 + tid;
        float q[4];
#pragma unroll
        for (int c = 0; c < 4; c++) q[c] = qb[(size_t)c * NPIX + n];
        float kvv[16];
#pragma unroll
        for (int d = 0; d < 16; d++) kvv[d] = kb[(size_t)d * NPIX + n];

#pragma unroll
        for (int c = 0; c < 4; c++) qss[c] = fmaf(q[c], q[c], qss[c]);
        if (grp == 0) {
#pragma unroll
            for (int d = 0; d < 16; d++) kss[d] = fmaf(kvv[d], kvv[d], kss[d]);
        }
#pragma unroll
        for (int c = 0; c < 4; c++)
#pragma unroll
            for (int d = 0; d < 16; d++)
                acc[c][d] = fmaf(q[c], kvv[d], acc[c][d]);
    }

#pragma unroll
    for (int c = 0; c < 4; c++) {
#pragma unroll
        for (int d = 0; d < 16; d++)
#pragma unroll
            for (int o = 16; o; o >>= 1)
                acc[c][d] += __shfl_xor_sync(0xffffffffu, acc[c][d], o);
#pragma unroll
        for (int o = 16; o; o >>= 1)
            qss[c] += __shfl_xor_sync(0xffffffffu, qss[c], o);
    }
    if (grp == 0) {
#pragma unroll
        for (int d = 0; d < 16; d++)
#pragma unroll
            for (int o = 16; o; o >>= 1)
                kss[d] += __shfl_xor_sync(0xffffffffu, kss[d], o);
    }

    __shared__ float red[4][64];
    __shared__ float ssred[4][20];
    if (lane == 0) {
#pragma unroll
        for (int c = 0; c < 4; c++) {
#pragma unroll
            for (int d = 0; d < 16; d++) red[wid][c * 16 + d] = acc[c][d];
            ssred[wid][16 + c] = qss[c];
        }
        if (grp == 0)
#pragma unroll
            for (int d = 0; d < 16; d++) ssred[wid][d] = kss[d];
    }
    __syncthreads();

    if (tid < 64) {
        float s = 0.f;
#pragma unroll
        for (int w = 0; w < 4; w++) s += red[w][tid];
        Gpart[((size_t)(bh * 3 + grp) * NSLICE + slice) * 64 + tid] = s;
    } else if (tid < 68) {
        const int c = tid - 64;
        float s = 0.f;
#pragma unroll
        for (int w = 0; w < 4; w++) s += ssred[w][16 + c];
        SSpart[((size_t)bh * NSLICE + slice) * 28 + 16 + grp * 4 + c] = s;
    } else if (tid < 84 && grp == 0) {
        const int d = tid - 68;
        float s = 0.f;
#pragma unroll
        for (int w = 0; w < 4; w++) s += ssred[w][d];
        SSpart[((size_t)bh * NSLICE + slice) * 28 + d] = s;
    }
}

// ------- gram/ss reduce + softmax + fold projection (emit bf16 hi/lo) -------
__global__ void softmax_fold_kernel(const float* __restrict__ Gpart,
                                    const float* __restrict__ SSpart,
                                    const float* __restrict__ temp,
                                    const float* __restrict__ w_ph, const float* __restrict__ w_pl,
                                    unsigned* __restrict__ McHi, unsigned* __restrict__ McLo)
{
    __shared__ float Gh[1024];
    __shared__ float Gl[512];
    __shared__ float Ah[1024];
    __shared__ float Al[512];
    __shared__ float knS[128];
    int t = threadIdx.x;

    for (int idx = t; idx < 1536; idx += 256) {
        int bh = idx / 192, rem = idx % 192;
        int grp = rem / 64, cd = rem % 64;
        float s = 0.f;
        for (int sl = 0; sl < NSLICE; sl++)
            s += Gpart[((size_t)(bh * 3 + grp) * NSLICE + sl) * 64 + cd];
        int c = cd / 16, d = cd % 16;
        if (grp < 2) Gh[(bh * 8 + grp * 4 + c) * 16 + d] = s;
        else         Gl[(bh * 4 + c) * 16 + d] = s;
    }
    if (t < 128) {
        int bh = t >> 4, d = t & 15;
        float s = 0.f;
        for (int sl = 0; sl < NSLICE; sl++)
            s += SSpart[((size_t)bh * NSLICE + sl) * 28 + d];
        knS[t] = fmaxf(sqrtf(s), 1e-12f);
    }
    __syncthreads();

    if (t < 96) {
        int b = t / 48, rem = t % 48, head = rem / 12, c = rem % 12;
        int bh = b * 4 + head;
        const float* Grow;
        float* Arow;
        int qpos;
        if (c < 8) {
            qpos = 16 + c;
            Grow = Gh + (bh * 8 + c) * 16;
            Arow = Ah + (bh * 8 + c) * 16;
        } else {
            qpos = 24 + (c - 8);
            Grow = Gl + (bh * 4 + c - 8) * 16;
            Arow = Al + (bh * 4 + c - 8) * 16;
        }
        float nq = 0.f;
        for (int sl = 0; sl < NSLICE; sl++)
            nq += SSpart[((size_t)bh * NSLICE + sl) * 28 + qpos];
        float qn = fmaxf(sqrtf(nq), 1e-12f);
        float tp = temp[head];
        float sc[16];
        float mx = -1e30f;
#pragma unroll
        for (int d = 0; d < 16; d++) {
            sc[d] = Grow[d] / (qn * knS[bh * 16 + d]) * tp;
            mx = fmaxf(mx, sc[d]);
        }
        float sum = 0.f;
#pragma unroll
        for (int d = 0; d < 16; d++) { sc[d] = expf(sc[d] - mx); sum += sc[d]; }
        float inv = 1.f / sum;
#pragma unroll
        for (int d = 0; d < 16; d++) Arow[d] = sc[d] * inv;
    }
    __syncthreads();

    for (int idx = t; idx < 2 * 192 * 32; idx += 256) {
        int b = idx / (192 * 32), rr = idx % (192 * 32);
        int o = rr / 32, dp = rr % 32;
        float s[2];
#pragma unroll
        for (int e = 0; e < 2; e++) {
            int dfull = dp * 2 + e;
            int head = dfull >> 4, dd = dfull & 15;
            float v = 0.f;
            if (o < 128) {
#pragma unroll
                for (int cp = 0; cp < 8; cp++)
                    v += w_ph[o * 32 + head * 8 + cp] * Ah[((b * 4 + head) * 8 + cp) * 16 + dd];
            } else {
                int ol = o - 128;
#pragma unroll
                for (int cp = 0; cp < 4; cp++)
                    v += w_pl[ol * 16 + head * 4 + cp] * Al[((b * 4 + head) * 4 + cp) * 16 + dd];
            }
            s[e] = v;
        }
        uint32_t h0, l0, h1, l1;
        split_bf16(s[0], h0, l0);
        split_bf16(s[1], h1, l1);
        McHi[(size_t)(b * 192 + o) * 36 + dp] = h0 | (h1 << 16);
        McLo[(size_t)(b * 192 + o) * 36 + dp] = l0 | (l1 << 16);
    }
}

// ---------------- host launcher ---------------------------------------------
extern "C" void kernel_launch(void* const* d_in, const int* in_sizes, int n_in,
                              void* d_out, int out_size)
{
    const float* x      = (const float*)d_in[0];
    const float* x_h    = (const float*)d_in[1];
    const float* x_l    = (const float*)d_in[2];
    const float* w_kv   = (const float*)d_in[3];
    const float* kv_dw1 = (const float*)d_in[4];
    const float* kv_dw2 = (const float*)d_in[5];
    const float* kv_dw3 = (const float*)d_in[6];
    const float* w_qh   = (const float*)d_in[7];
    const float* qh_dw1 = (const float*)d_in[8];
    const float* qh_dw2 = (const float*)d_in[9];
    const float* qh_dw3 = (const float*)d_in[10];
    const float* w_ql   = (const float*)d_in[11];
    const float* ql_dw1 = (const float*)d_in[12];
    const float* ql_dw2 = (const float*)d_in[13];
    const float* ql_dw3 = (const float*)d_in[14];
    const float* w_ph   = (const float*)d_in[15];
    const float* w_pl   = (const float*)d_in[16];
    const float* temp   = (const float*)d_in[17];
    float* out = (float*)d_out;

    float *kv_pre, *kv, *qh_pre, *qh, *ql_pre, *ql, *Gpart, *SSpart, *dmy;
    float *WtQH, *WtQL;
    unsigned *WhiP, *WloP, *McHi, *McLo;
    cudaGetSymbolAddress((void**)&kv_pre, g_kv_pre);
    cudaGetSymbolAddress((void**)&kv,     g_kv);
    cudaGetSymbolAddress((void**)&qh_pre, g_qh_pre);
    cudaGetSymbolAddress((void**)&qh,     g_qh);
    cudaGetSymbolAddress((void**)&ql_pre, g_ql_pre);
    cudaGetSymbolAddress((void**)&ql,     g_ql);
    cudaGetSymbolAddress((void**)&Gpart,  g_Gpart);
    cudaGetSymbolAddress((void**)&SSpart, g_SSpart);
    cudaGetSymbolAddress((void**)&McHi,   g_McHi);
    cudaGetSymbolAddress((void**)&McLo,   g_McLo);
    cudaGetSymbolAddress((void**)&WhiP,   g_WhiP);
    cudaGetSymbolAddress((void**)&WloP,   g_WloP);
    cudaGetSymbolAddress((void**)&WtQH,   g_WtQH);
    cudaGetSymbolAddress((void**)&WtQL,   g_WtQL);
    cudaGetSymbolAddress((void**)&dmy,    g_dummy);

    cudaFuncSetAttribute(mega_kernel,
                         cudaFuncAttributeMaxDynamicSharedMemorySize, KV_SMEM);
    cudaFuncSetAttribute(fin_mma_kernel,
                         cudaFuncAttributeMaxDynamicSharedMemorySize, FG_SMEM);

    // weight prep: bf16 hi/lo packing for kv + transposes for qh/ql
    prep_kernel<<<84, 256>>>(w_kv, w_qh, w_ql, WhiP, WloP, WtQH, WtQL);

    // shim: keep profiler window (launch #4) on pyramid to verify the fix
    dummy_kernel<<<1, 32>>>(dmy);

    // merged launch: kv tensor GEMM + qh/ql fp32 GEMMs (bid-range mapping)
    mega_kernel<<<3072, 256, KV_SMEM>>>(x, WhiP, WloP, kv, kv_pre,
                                        x_h, WtQH, qh, qh_pre,
                                        x_l, WtQL, ql, ql_pre);

    // pyramid depthwise convs (4 px/thread, float4 windows)
    pyramid_all_kernel<<<dim3(64, 1, 264), 256>>>(
        kv_pre, kv, qh_pre, qh, ql_pre, ql,
        kv_dw1, kv_dw2, kv_dw3, qh_dw1, qh_dw2, qh_dw3, ql_dw1, ql_dw2, ql_dw3);

    // fused Gram + sum-of-squares: barrier-free per-team blocks, L2-shared k
    gram_ss_kernel<<<24 * NSLICE, 128>>>(qh, ql, kv, Gpart, SSpart);

    // reduce + softmax + fold attention -> bf16 hi/lo projection matrix
    softmax_fold_kernel<<<1, 256>>>(Gpart, SSpart, temp, w_ph, w_pl, McHi, McLo);

    // final attention-apply + projection (k-pair-packed B, conflict-free)
    fin_mma_kernel<<<dim3(512, 2), 384, FG_SMEM>>>(
        kv, McHi, McLo, out, out + 2 * 128 * NPIX);
}